// round 2
// baseline (speedup 1.0000x reference)
#include <cuda_runtime.h>

// KAN 1-D conv, B=32 I=8 O=32 W=8192 K=5 Wo=8188, 9 channels (silu + 8 cubic B-splines).
// R2: register-cached features (aligned LDS.128), o-pair packed fma.rn.f32x2,
//     TILE_W=64 for 3 blocks/SM.

#define B_DIM 32
#define I_DIM 8
#define O_DIM 32
#define W_IN 8192
#define KSZ 5
#define W_OUT (W_IN - KSZ + 1)   // 8188
#define NC 9
#define TILE_W 64
#define FP (TILE_W + KSZ - 1)    // 68
#define NTHREADS 128
#define NTILES ((W_OUT + TILE_W - 1) / TILE_W)   // 128

__host__ __device__ constexpr float gridc(int j) {
    return (float)(j - 3) * 0.4f - 1.0f;
}

#define WC_ELEMS (I_DIM * KSZ * NC * O_DIM)   // 11520
#define FS_ELEMS (I_DIM * NC * FP)            // 4896
#define SMEM_FLOATS (WC_ELEMS + FS_ELEMS)     // 16416 -> 65664 B

__device__ __forceinline__ unsigned long long splat2(float f) {
    unsigned long long r;
    asm("mov.b64 %0, {%1, %1};" : "=l"(r) : "r"(__float_as_uint(f)));
    return r;
}
__device__ __forceinline__ void ffma2(unsigned long long& d,
                                      unsigned long long a,
                                      unsigned long long b) {
    asm("fma.rn.f32x2 %0, %1, %2, %0;" : "+l"(d) : "l"(a), "l"(b));
}
__device__ __forceinline__ float lo32(unsigned long long v) {
    return __uint_as_float((unsigned)(v & 0xffffffffull));
}
__device__ __forceinline__ float hi32(unsigned long long v) {
    return __uint_as_float((unsigned)(v >> 32));
}

__global__ __launch_bounds__(NTHREADS)
void kan_conv1d_kernel(const float* __restrict__ x,
                       const float* __restrict__ base_weight,
                       const float* __restrict__ spline_weight,
                       const float* __restrict__ spline_scaler,
                       float* __restrict__ out)
{
    extern __shared__ float smem[];
    float* Wc = smem;                 // [I][K][NC][O]   o contiguous
    float* Fs = smem + WC_ELEMS;      // [I][NC][FP]

    const int tid = threadIdx.x;
    const int b   = blockIdx.y;
    const int w0  = blockIdx.x * TILE_W;

    // ---- Phase 1: fuse weights into smem (idx enumerates (o,i,k) row-major) ----
    for (int idx = tid; idx < O_DIM * I_DIM * KSZ; idx += NTHREADS) {
        int k = idx % KSZ;
        int r = idx / KSZ;
        int i = r % I_DIM;
        int o = r / I_DIM;
        float bw = base_weight[idx];
        float sc = spline_scaler[idx];
        float* dst = &Wc[((i * KSZ + k) * NC) * O_DIM + o];
        dst[0] = bw;
        const float* sw = &spline_weight[idx * 8];
        #pragma unroll
        for (int c = 0; c < 8; c++)
            dst[(c + 1) * O_DIM] = sw[c] * sc;
    }

    // ---- Phase 2: per-element features ----
    for (int e = tid; e < I_DIM * FP; e += NTHREADS) {
        int i = e / FP;
        int p = e % FP;
        int gw = w0 + p;
        float xv = (gw < W_IN) ? x[(b * I_DIM + i) * W_IN + gw] : 0.0f;

        float* f = &Fs[i * NC * FP + p];
        f[0] = xv / (1.0f + __expf(-xv));

        float b0[11];
        #pragma unroll
        for (int j = 0; j < 11; j++)
            b0[j] = (xv >= gridc(j) && xv < gridc(j + 1)) ? 1.0f : 0.0f;
        float b1[10];
        #pragma unroll
        for (int j = 0; j < 10; j++) {
            float l = (xv - gridc(j))     * (1.0f / (gridc(j + 1) - gridc(j)));
            float r = (gridc(j + 2) - xv) * (1.0f / (gridc(j + 2) - gridc(j + 1)));
            b1[j] = l * b0[j] + r * b0[j + 1];
        }
        float b2[9];
        #pragma unroll
        for (int j = 0; j < 9; j++) {
            float l = (xv - gridc(j))     * (1.0f / (gridc(j + 2) - gridc(j)));
            float r = (gridc(j + 3) - xv) * (1.0f / (gridc(j + 3) - gridc(j + 1)));
            b2[j] = l * b1[j] + r * b1[j + 1];
        }
        #pragma unroll
        for (int j = 0; j < 8; j++) {
            float l = (xv - gridc(j))     * (1.0f / (gridc(j + 3) - gridc(j)));
            float r = (gridc(j + 4) - xv) * (1.0f / (gridc(j + 4) - gridc(j + 1)));
            f[(j + 1) * FP] = l * b2[j] + r * b2[j + 1];
        }
    }
    __syncthreads();

    // ---- Phase 3: MAC. Thread owns o in [o0, o0+4), w in [wt*4, wt*4+4). ----
    const int wt = tid & 15;      // 16 w-lanes * 4 w each = 64 w
    const int og = tid >> 4;      // 8 o-groups * 4 o each = 32 o
    const int o0 = og * 4;

    // acc[p][u]: o-pair p (o0+2p, o0+2p+1) packed in f32x2 lanes, w = wt*4+u
    unsigned long long acc[2][4];
    #pragma unroll
    for (int p = 0; p < 2; p++)
        #pragma unroll
        for (int u = 0; u < 4; u++)
            acc[p][u] = 0ull;

    #pragma unroll 1
    for (int i = 0; i < I_DIM; i++) {
        #pragma unroll 1
        for (int c = 0; c < NC; c++) {
            // 8 consecutive feature positions [wt*4, wt*4+8) — two aligned LDS.128
            const float4* f4 = (const float4*)(Fs + (i * NC + c) * FP + wt * 4);
            float4 fa = f4[0];
            float4 fb = f4[1];
            unsigned long long fs[8];
            fs[0] = splat2(fa.x); fs[1] = splat2(fa.y);
            fs[2] = splat2(fa.z); fs[3] = splat2(fa.w);
            fs[4] = splat2(fb.x); fs[5] = splat2(fb.y);
            fs[6] = splat2(fb.z); fs[7] = splat2(fb.w);

            #pragma unroll
            for (int k = 0; k < KSZ; k++) {
                const unsigned long long* wp = (const unsigned long long*)
                    &Wc[((i * KSZ + k) * NC + c) * O_DIM + o0];
                unsigned long long w01 = wp[0];
                unsigned long long w23 = wp[1];
                #pragma unroll
                for (int u = 0; u < 4; u++) {
                    ffma2(acc[0][u], w01, fs[u + k]);
                    ffma2(acc[1][u], w23, fs[u + k]);
                }
            }
        }
    }

    // ---- Phase 4: store. 4 o-rows x 4 consecutive w per thread. ----
    const int wbase = w0 + wt * 4;
    const bool full = (w0 + TILE_W <= W_OUT);
    #pragma unroll
    for (int p = 0; p < 2; p++) {
        float l0 = lo32(acc[p][0]), l1 = lo32(acc[p][1]),
              l2 = lo32(acc[p][2]), l3 = lo32(acc[p][3]);
        float h0 = hi32(acc[p][0]), h1 = hi32(acc[p][1]),
              h2 = hi32(acc[p][2]), h3 = hi32(acc[p][3]);
        int olo = o0 + 2 * p;
        float* rlo = out + ((size_t)(b * O_DIM + olo)) * W_OUT + wbase;
        float* rhi = rlo + W_OUT;
        if (full) {
            *(float4*)rlo = make_float4(l0, l1, l2, l3);
            *(float4*)rhi = make_float4(h0, h1, h2, h3);
        } else {
            float lv[4] = {l0, l1, l2, l3};
            float hv[4] = {h0, h1, h2, h3};
            #pragma unroll
            for (int u = 0; u < 4; u++) {
                if (wbase + u < W_OUT) {
                    rlo[u] = lv[u];
                    rhi[u] = hv[u];
                }
            }
        }
    }
}

extern "C" void kernel_launch(void* const* d_in, const int* in_sizes, int n_in,
                              void* d_out, int out_size)
{
    const float* x             = (const float*)d_in[0];
    const float* base_weight   = (const float*)d_in[1];
    const float* spline_weight = (const float*)d_in[2];
    const float* spline_scaler = (const float*)d_in[3];
    float* out = (float*)d_out;

    size_t smem_bytes = SMEM_FLOATS * sizeof(float);   // 65664
    cudaFuncSetAttribute(kan_conv1d_kernel,
                         cudaFuncAttributeMaxDynamicSharedMemorySize,
                         (int)smem_bytes);

    dim3 grid(NTILES, B_DIM);   // 128 x 32
    kan_conv1d_kernel<<<grid, NTHREADS, smem_bytes>>>(
        x, base_weight, spline_weight, spline_scaler, out);
}

// round 4
// speedup vs baseline: 1.3561x; 1.3561x over previous
#include <cuda_runtime.h>

// KAN 1-D conv, B=32 I=8 O=32 W=8192 K=5 Wo=8188, 9 channels (silu + 8 cubic B-splines).
// R3 resubmit (prior bench was an infra failure): 4o x 8w register tile,
// o-pair fma.rn.f32x2, packed LDS.64 weight pairs, pipelined c-loop.
// TILE_W=128, 2 blocks/SM.

#define B_DIM 32
#define I_DIM 8
#define O_DIM 32
#define W_IN 8192
#define KSZ 5
#define W_OUT (W_IN - KSZ + 1)   // 8188
#define NC 9
#define TILE_W 128
#define FP (TILE_W + KSZ - 1)    // 132
#define NTHREADS 128
#define NTILES ((W_OUT + TILE_W - 1) / TILE_W)   // 64

__host__ __device__ constexpr float gridc(int j) {
    return (float)(j - 3) * 0.4f - 1.0f;
}

#define WC_ELEMS (I_DIM * KSZ * NC * O_DIM)   // 11520 (45KB)
#define FS_ELEMS (I_DIM * NC * FP)            // 9504  (37KB)
#define SMEM_FLOATS (WC_ELEMS + FS_ELEMS)     // 21024 -> 84096 B

__device__ __forceinline__ unsigned long long splat2(float f) {
    unsigned long long r;
    asm("mov.b64 %0, {%1, %1};" : "=l"(r) : "r"(__float_as_uint(f)));
    return r;
}
__device__ __forceinline__ void ffma2(unsigned long long& d,
                                      unsigned long long a,
                                      unsigned long long b) {
    asm("fma.rn.f32x2 %0, %1, %2, %0;" : "+l"(d) : "l"(a), "l"(b));
}
__device__ __forceinline__ float lo32(unsigned long long v) {
    return __uint_as_float((unsigned)(v & 0xffffffffull));
}
__device__ __forceinline__ float hi32(unsigned long long v) {
    return __uint_as_float((unsigned)(v >> 32));
}

__global__ __launch_bounds__(NTHREADS)
void kan_conv1d_kernel(const float* __restrict__ x,
                       const float* __restrict__ base_weight,
                       const float* __restrict__ spline_weight,
                       const float* __restrict__ spline_scaler,
                       float* __restrict__ out)
{
    extern __shared__ float smem[];
    float* Wc = smem;                 // [I][K][NC][O]   o contiguous
    float* Fs = smem + WC_ELEMS;      // [I][NC][FP]

    const int tid = threadIdx.x;
    const int b   = blockIdx.y;
    const int w0  = blockIdx.x * TILE_W;

    // ---- Phase 1: fuse weights into smem (idx enumerates (o,i,k) row-major) ----
    for (int idx = tid; idx < O_DIM * I_DIM * KSZ; idx += NTHREADS) {
        int k = idx % KSZ;
        int r = idx / KSZ;
        int i = r % I_DIM;
        int o = r / I_DIM;
        float bw = base_weight[idx];
        float sc = spline_scaler[idx];
        float* dst = &Wc[((i * KSZ + k) * NC) * O_DIM + o];
        dst[0] = bw;
        const float* sw = &spline_weight[idx * 8];
        #pragma unroll
        for (int c = 0; c < 8; c++)
            dst[(c + 1) * O_DIM] = sw[c] * sc;
    }

    // ---- Phase 2: per-element features (silu + 8 cubic B-spline bases) ----
    for (int e = tid; e < I_DIM * FP; e += NTHREADS) {
        int i = e / FP;
        int p = e % FP;
        int gw = w0 + p;
        float xv = (gw < W_IN) ? x[(b * I_DIM + i) * W_IN + gw] : 0.0f;

        float* f = &Fs[i * NC * FP + p];
        f[0] = xv / (1.0f + __expf(-xv));

        float b0[11];
        #pragma unroll
        for (int j = 0; j < 11; j++)
            b0[j] = (xv >= gridc(j) && xv < gridc(j + 1)) ? 1.0f : 0.0f;
        float b1[10];
        #pragma unroll
        for (int j = 0; j < 10; j++) {
            float l = (xv - gridc(j))     * (1.0f / (gridc(j + 1) - gridc(j)));
            float r = (gridc(j + 2) - xv) * (1.0f / (gridc(j + 2) - gridc(j + 1)));
            b1[j] = l * b0[j] + r * b0[j + 1];
        }
        float b2[9];
        #pragma unroll
        for (int j = 0; j < 9; j++) {
            float l = (xv - gridc(j))     * (1.0f / (gridc(j + 2) - gridc(j)));
            float r = (gridc(j + 3) - xv) * (1.0f / (gridc(j + 3) - gridc(j + 1)));
            b2[j] = l * b1[j] + r * b1[j + 1];
        }
        #pragma unroll
        for (int j = 0; j < 8; j++) {
            float l = (xv - gridc(j))     * (1.0f / (gridc(j + 3) - gridc(j)));
            float r = (gridc(j + 4) - xv) * (1.0f / (gridc(j + 4) - gridc(j + 1)));
            f[(j + 1) * FP] = l * b2[j] + r * b2[j + 1];
        }
    }
    __syncthreads();

    // ---- Phase 3: MAC. Thread owns o in [o0,o0+4), w in [wt*8, wt*8+8). ----
    const int wt = tid & 15;      // 16 w-lanes * 8 w = 128 w
    const int og = tid >> 4;      // 8 o-groups * 4 o = 32 o
    const int o0 = og * 4;

    // acc[p][u]: o-pair p = (o0+2p, o0+2p+1) packed in f32x2 lanes, w = wt*8+u
    unsigned long long acc[2][8];
    #pragma unroll
    for (int p = 0; p < 2; p++)
        #pragma unroll
        for (int u = 0; u < 8; u++)
            acc[p][u] = 0ull;

    #pragma unroll 1
    for (int i = 0; i < I_DIM; i++) {
        #pragma unroll 3
        for (int c = 0; c < NC; c++) {
            // 12 consecutive feature positions [wt*8, wt*8+12) — three aligned LDS.128
            const float4* f4 = (const float4*)(Fs + (i * NC + c) * FP + wt * 8);
            float4 fa = f4[0];
            float4 fb = f4[1];
            float4 fc = f4[2];
            unsigned long long fs[12];
            fs[0]  = splat2(fa.x); fs[1]  = splat2(fa.y);
            fs[2]  = splat2(fa.z); fs[3]  = splat2(fa.w);
            fs[4]  = splat2(fb.x); fs[5]  = splat2(fb.y);
            fs[6]  = splat2(fb.z); fs[7]  = splat2(fb.w);
            fs[8]  = splat2(fc.x); fs[9]  = splat2(fc.y);
            fs[10] = splat2(fc.z); fs[11] = splat2(fc.w);

            #pragma unroll
            for (int k = 0; k < KSZ; k++) {
                const unsigned long long* wp = (const unsigned long long*)
                    &Wc[((i * KSZ + k) * NC + c) * O_DIM + o0];
                unsigned long long w01 = wp[0];
                unsigned long long w23 = wp[1];
                #pragma unroll
                for (int u = 0; u < 8; u++) {
                    ffma2(acc[0][u], w01, fs[u + k]);
                    ffma2(acc[1][u], w23, fs[u + k]);
                }
            }
        }
    }

    // ---- Phase 4: store. 4 o-rows x 8 consecutive w per thread. ----
    const int wbase = w0 + wt * 8;
    const bool full = (w0 + TILE_W <= W_OUT);
    #pragma unroll
    for (int p = 0; p < 2; p++) {
        float v[2][8];
        #pragma unroll
        for (int u = 0; u < 8; u++) {
            v[0][u] = lo32(acc[p][u]);
            v[1][u] = hi32(acc[p][u]);
        }
        #pragma unroll
        for (int h = 0; h < 2; h++) {
            int o = o0 + 2 * p + h;
            float* row = out + ((size_t)(b * O_DIM + o)) * W_OUT + wbase;
            if (full) {
                *(float4*)(row)     = make_float4(v[h][0], v[h][1], v[h][2], v[h][3]);
                *(float4*)(row + 4) = make_float4(v[h][4], v[h][5], v[h][6], v[h][7]);
            } else {
                #pragma unroll
                for (int u = 0; u < 8; u++)
                    if (wbase + u < W_OUT) row[u] = v[h][u];
            }
        }
    }
}

extern "C" void kernel_launch(void* const* d_in, const int* in_sizes, int n_in,
                              void* d_out, int out_size)
{
    const float* x             = (const float*)d_in[0];
    const float* base_weight   = (const float*)d_in[1];
    const float* spline_weight = (const float*)d_in[2];
    const float* spline_scaler = (const float*)d_in[3];
    float* out = (float*)d_out;

    size_t smem_bytes = SMEM_FLOATS * sizeof(float);   // 84096
    cudaFuncSetAttribute(kan_conv1d_kernel,
                         cudaFuncAttributeMaxDynamicSharedMemorySize,
                         (int)smem_bytes);

    dim3 grid(NTILES, B_DIM);   // 64 x 32
    kan_conv1d_kernel<<<grid, NTHREADS, smem_bytes>>>(
        x, base_weight, spline_weight, spline_scaler, out);
}

// round 5
// speedup vs baseline: 1.3862x; 1.0222x over previous
#include <cuda_runtime.h>

// KAN 1-D conv, B=32 I=8 O=32 W=8192 K=5 Wo=8188, 9 channels (silu + 8 cubic B-splines).
// R5: conflict-free interleaved w-groups (w = wt*4+u + 64g), float4 weight-quad
// loads (ulonglong2 -> two f32x2 pairs), o-pair fma.rn.f32x2. TILE_W=128.

#define B_DIM 32
#define I_DIM 8
#define O_DIM 32
#define W_IN 8192
#define KSZ 5
#define W_OUT (W_IN - KSZ + 1)   // 8188
#define NC 9
#define TILE_W 128
#define HALF_W 64
#define FP (TILE_W + KSZ - 1)    // 132
#define NTHREADS 128
#define NTILES ((W_OUT + TILE_W - 1) / TILE_W)   // 64

__host__ __device__ constexpr float gridc(int j) {
    return (float)(j - 3) * 0.4f - 1.0f;
}

#define WC_ELEMS (I_DIM * KSZ * NC * O_DIM)   // 11520 (45KB)
#define FS_ELEMS (I_DIM * NC * FP)            // 9504  (37KB)
#define SMEM_FLOATS (WC_ELEMS + FS_ELEMS)     // 21024 -> 84096 B

__device__ __forceinline__ unsigned long long splat2(float f) {
    unsigned long long r;
    asm("mov.b64 %0, {%1, %1};" : "=l"(r) : "r"(__float_as_uint(f)));
    return r;
}
__device__ __forceinline__ void ffma2(unsigned long long& d,
                                      unsigned long long a,
                                      unsigned long long b) {
    asm("fma.rn.f32x2 %0, %1, %2, %0;" : "+l"(d) : "l"(a), "l"(b));
}
__device__ __forceinline__ float lo32(unsigned long long v) {
    return __uint_as_float((unsigned)(v & 0xffffffffull));
}
__device__ __forceinline__ float hi32(unsigned long long v) {
    return __uint_as_float((unsigned)(v >> 32));
}

__global__ __launch_bounds__(NTHREADS)
void kan_conv1d_kernel(const float* __restrict__ x,
                       const float* __restrict__ base_weight,
                       const float* __restrict__ spline_weight,
                       const float* __restrict__ spline_scaler,
                       float* __restrict__ out)
{
    extern __shared__ float smem[];
    float* Wc = smem;                 // [I][K][NC][O]   o contiguous
    float* Fs = smem + WC_ELEMS;      // [I][NC][FP]

    const int tid = threadIdx.x;
    const int b   = blockIdx.y;
    const int w0  = blockIdx.x * TILE_W;

    // ---- Phase 1: fuse weights into smem (idx enumerates (o,i,k) row-major) ----
    for (int idx = tid; idx < O_DIM * I_DIM * KSZ; idx += NTHREADS) {
        int k = idx % KSZ;
        int r = idx / KSZ;
        int i = r % I_DIM;
        int o = r / I_DIM;
        float bw = base_weight[idx];
        float sc = spline_scaler[idx];
        float* dst = &Wc[((i * KSZ + k) * NC) * O_DIM + o];
        dst[0] = bw;
        const float* sw = &spline_weight[idx * 8];
        #pragma unroll
        for (int c = 0; c < 8; c++)
            dst[(c + 1) * O_DIM] = sw[c] * sc;
    }

    // ---- Phase 2: per-element features (silu + 8 cubic B-spline bases) ----
    for (int e = tid; e < I_DIM * FP; e += NTHREADS) {
        int i = e / FP;
        int p = e % FP;
        int gw = w0 + p;
        float xv = (gw < W_IN) ? x[(b * I_DIM + i) * W_IN + gw] : 0.0f;

        float* f = &Fs[i * NC * FP + p];
        f[0] = xv / (1.0f + __expf(-xv));

        float b0[11];
        #pragma unroll
        for (int j = 0; j < 11; j++)
            b0[j] = (xv >= gridc(j) && xv < gridc(j + 1)) ? 1.0f : 0.0f;
        float b1[10];
        #pragma unroll
        for (int j = 0; j < 10; j++) {
            float l = (xv - gridc(j))     * (1.0f / (gridc(j + 1) - gridc(j)));
            float r = (gridc(j + 2) - xv) * (1.0f / (gridc(j + 2) - gridc(j + 1)));
            b1[j] = l * b0[j] + r * b0[j + 1];
        }
        float b2[9];
        #pragma unroll
        for (int j = 0; j < 9; j++) {
            float l = (xv - gridc(j))     * (1.0f / (gridc(j + 2) - gridc(j)));
            float r = (gridc(j + 3) - xv) * (1.0f / (gridc(j + 3) - gridc(j + 1)));
            b2[j] = l * b1[j] + r * b1[j + 1];
        }
        #pragma unroll
        for (int j = 0; j < 8; j++) {
            float l = (xv - gridc(j))     * (1.0f / (gridc(j + 3) - gridc(j)));
            float r = (gridc(j + 4) - xv) * (1.0f / (gridc(j + 4) - gridc(j + 1)));
            f[(j + 1) * FP] = l * b2[j] + r * b2[j + 1];
        }
    }
    __syncthreads();

    // ---- Phase 3: MAC. Thread owns o in [o0,o0+4), w = wt*4+u+64g (u<4, g<2). ----
    const int wt = tid & 15;      // 16 w-lanes
    const int og = tid >> 4;      // 8 o-groups * 4 o = 32 o
    const int o0 = og * 4;

    // acc[g][p][u]: group g, o-pair p = (o0+2p, o0+2p+1) in f32x2 lanes, w = wt*4+u+64g
    unsigned long long acc[2][2][4];
    #pragma unroll
    for (int g = 0; g < 2; g++)
        #pragma unroll
        for (int p = 0; p < 2; p++)
            #pragma unroll
            for (int u = 0; u < 4; u++)
                acc[g][p][u] = 0ull;

    #pragma unroll 1
    for (int i = 0; i < I_DIM; i++) {
        #pragma unroll 3
        for (int c = 0; c < NC; c++) {
            const float* frow = Fs + (i * NC + c) * FP + wt * 4;
            // group A: positions [wt*4, wt*4+8)   — lane stride 16B, conflict-free
            float4 a0 = *(const float4*)(frow);
            float4 a1 = *(const float4*)(frow + 4);
            // group B: positions [wt*4+64, wt*4+72)
            float4 c0 = *(const float4*)(frow + HALF_W);
            float4 c1 = *(const float4*)(frow + HALF_W + 4);

            unsigned long long fsA[8], fsB[8];
            fsA[0] = splat2(a0.x); fsA[1] = splat2(a0.y);
            fsA[2] = splat2(a0.z); fsA[3] = splat2(a0.w);
            fsA[4] = splat2(a1.x); fsA[5] = splat2(a1.y);
            fsA[6] = splat2(a1.z); fsA[7] = splat2(a1.w);
            fsB[0] = splat2(c0.x); fsB[1] = splat2(c0.y);
            fsB[2] = splat2(c0.z); fsB[3] = splat2(c0.w);
            fsB[4] = splat2(c1.x); fsB[5] = splat2(c1.y);
            fsB[6] = splat2(c1.z); fsB[7] = splat2(c1.w);

            #pragma unroll
            for (int k = 0; k < KSZ; k++) {
                // one LDS.128 = weight quad {o0..o0+3} = two f32x2 pairs
                ulonglong2 wq = *(const ulonglong2*)
                    &Wc[((i * KSZ + k) * NC + c) * O_DIM + o0];
                #pragma unroll
                for (int u = 0; u < 4; u++) {
                    ffma2(acc[0][0][u], wq.x, fsA[u + k]);
                    ffma2(acc[0][1][u], wq.y, fsA[u + k]);
                    ffma2(acc[1][0][u], wq.x, fsB[u + k]);
                    ffma2(acc[1][1][u], wq.y, fsB[u + k]);
                }
            }
        }
    }

    // ---- Phase 4: store. 4 o-rows x (2 groups x 4 w) per thread. ----
    #pragma unroll
    for (int g = 0; g < 2; g++) {
        const int wbase = w0 + wt * 4 + g * HALF_W;
        const bool full = (wbase + 4 <= W_OUT);
        #pragma unroll
        for (int p = 0; p < 2; p++) {
            float lv[4], hv[4];
            #pragma unroll
            for (int u = 0; u < 4; u++) {
                lv[u] = lo32(acc[g][p][u]);
                hv[u] = hi32(acc[g][p][u]);
            }
            int olo = o0 + 2 * p;
            float* rlo = out + ((size_t)(b * O_DIM + olo)) * W_OUT + wbase;
            float* rhi = rlo + W_OUT;
            if (full) {
                *(float4*)rlo = make_float4(lv[0], lv[1], lv[2], lv[3]);
                *(float4*)rhi = make_float4(hv[0], hv[1], hv[2], hv[3]);
            } else {
                #pragma unroll
                for (int u = 0; u < 4; u++) {
                    if (wbase + u < W_OUT) {
                        rlo[u] = lv[u];
                        rhi[u] = hv[u];
                    }
                }
            }
        }
    }
}

extern "C" void kernel_launch(void* const* d_in, const int* in_sizes, int n_in,
                              void* d_out, int out_size)
{
    const float* x             = (const float*)d_in[0];
    const float* base_weight   = (const float*)d_in[1];
    const float* spline_weight = (const float*)d_in[2];
    const float* spline_scaler = (const float*)d_in[3];
    float* out = (float*)d_out;

    size_t smem_bytes = SMEM_FLOATS * sizeof(float);   // 84096
    cudaFuncSetAttribute(kan_conv1d_kernel,
                         cudaFuncAttributeMaxDynamicSharedMemorySize,
                         (int)smem_bytes);

    dim3 grid(NTILES, B_DIM);   // 64 x 32
    kan_conv1d_kernel<<<grid, NTHREADS, smem_bytes>>>(
        x, base_weight, spline_weight, spline_scaler, out);
}

// round 6
// speedup vs baseline: 1.3933x; 1.0051x over previous
#include <cuda_runtime.h>

// KAN 1-D conv, B=32 I=8 O=32 W=8192 K=5 Wo=8188, 9 channels (silu + 8 cubic B-splines).
// R6: 256 threads/block (16 warps/SM) to fix latency-boundness; 4o x 4w thread tile,
// o-pair fma.rn.f32x2, broadcast weight-quad LDS.128, conflict-free feature LDS.128.

#define B_DIM 32
#define I_DIM 8
#define O_DIM 32
#define W_IN 8192
#define KSZ 5
#define W_OUT (W_IN - KSZ + 1)   // 8188
#define NC 9
#define TILE_W 128
#define FP (TILE_W + KSZ - 1)    // 132
#define NTHREADS 256
#define NTILES ((W_OUT + TILE_W - 1) / TILE_W)   // 64

__host__ __device__ constexpr float gridc(int j) {
    return (float)(j - 3) * 0.4f - 1.0f;
}

#define WC_ELEMS (I_DIM * KSZ * NC * O_DIM)   // 11520 (45KB)
#define FS_ELEMS (I_DIM * NC * FP)            // 9504  (37KB)
#define SMEM_FLOATS (WC_ELEMS + FS_ELEMS)     // 21024 -> 84096 B

__device__ __forceinline__ unsigned long long splat2(float f) {
    unsigned long long r;
    asm("mov.b64 %0, {%1, %1};" : "=l"(r) : "r"(__float_as_uint(f)));
    return r;
}
__device__ __forceinline__ void ffma2(unsigned long long& d,
                                      unsigned long long a,
                                      unsigned long long b) {
    asm("fma.rn.f32x2 %0, %1, %2, %0;" : "+l"(d) : "l"(a), "l"(b));
}
__device__ __forceinline__ float lo32(unsigned long long v) {
    return __uint_as_float((unsigned)(v & 0xffffffffull));
}
__device__ __forceinline__ float hi32(unsigned long long v) {
    return __uint_as_float((unsigned)(v >> 32));
}

__global__ __launch_bounds__(NTHREADS)
void kan_conv1d_kernel(const float* __restrict__ x,
                       const float* __restrict__ base_weight,
                       const float* __restrict__ spline_weight,
                       const float* __restrict__ spline_scaler,
                       float* __restrict__ out)
{
    extern __shared__ float smem[];
    float* Wc = smem;                 // [I][K][NC][O]   o contiguous
    float* Fs = smem + WC_ELEMS;      // [I][NC][FP]

    const int tid = threadIdx.x;
    const int b   = blockIdx.y;
    const int w0  = blockIdx.x * TILE_W;

    // ---- Phase 1: fuse weights into smem (idx enumerates (o,i,k) row-major) ----
    for (int idx = tid; idx < O_DIM * I_DIM * KSZ; idx += NTHREADS) {
        int k = idx % KSZ;
        int r = idx / KSZ;
        int i = r % I_DIM;
        int o = r / I_DIM;
        float bw = base_weight[idx];
        float sc = spline_scaler[idx];
        float* dst = &Wc[((i * KSZ + k) * NC) * O_DIM + o];
        dst[0] = bw;
        const float* sw = &spline_weight[idx * 8];
        #pragma unroll
        for (int c = 0; c < 8; c++)
            dst[(c + 1) * O_DIM] = sw[c] * sc;
    }

    // ---- Phase 2: per-element features (silu + 8 cubic B-spline bases) ----
    for (int e = tid; e < I_DIM * FP; e += NTHREADS) {
        int i = e / FP;
        int p = e % FP;
        int gw = w0 + p;
        float xv = (gw < W_IN) ? x[(b * I_DIM + i) * W_IN + gw] : 0.0f;

        float* f = &Fs[i * NC * FP + p];
        f[0] = xv / (1.0f + __expf(-xv));

        float b0[11];
        #pragma unroll
        for (int j = 0; j < 11; j++)
            b0[j] = (xv >= gridc(j) && xv < gridc(j + 1)) ? 1.0f : 0.0f;
        float b1[10];
        #pragma unroll
        for (int j = 0; j < 10; j++) {
            float l = (xv - gridc(j))     * (1.0f / (gridc(j + 1) - gridc(j)));
            float r = (gridc(j + 2) - xv) * (1.0f / (gridc(j + 2) - gridc(j + 1)));
            b1[j] = l * b0[j] + r * b0[j + 1];
        }
        float b2[9];
        #pragma unroll
        for (int j = 0; j < 9; j++) {
            float l = (xv - gridc(j))     * (1.0f / (gridc(j + 2) - gridc(j)));
            float r = (gridc(j + 3) - xv) * (1.0f / (gridc(j + 3) - gridc(j + 1)));
            b2[j] = l * b1[j] + r * b1[j + 1];
        }
        #pragma unroll
        for (int j = 0; j < 8; j++) {
            float l = (xv - gridc(j))     * (1.0f / (gridc(j + 3) - gridc(j)));
            float r = (gridc(j + 4) - xv) * (1.0f / (gridc(j + 4) - gridc(j + 1)));
            f[(j + 1) * FP] = l * b2[j] + r * b2[j + 1];
        }
    }
    __syncthreads();

    // ---- Phase 3: MAC. Thread owns o in [o0,o0+4), w in [wt*4, wt*4+4). ----
    const int wt = tid & 31;      // 32 w-lanes * 4 w = 128 w
    const int og = tid >> 5;      // 8 o-groups * 4 o = 32 o   (uniform per warp)
    const int o0 = og * 4;

    // acc[p][u]: o-pair p = (o0+2p, o0+2p+1) packed in f32x2 lanes, w = wt*4+u
    unsigned long long acc[2][4];
    #pragma unroll
    for (int p = 0; p < 2; p++)
        #pragma unroll
        for (int u = 0; u < 4; u++)
            acc[p][u] = 0ull;

    #pragma unroll 1
    for (int i = 0; i < I_DIM; i++) {
        #pragma unroll 3
        for (int c = 0; c < NC; c++) {
            // 8 consecutive feature positions [wt*4, wt*4+8): two LDS.128,
            // lane stride 16B -> conflict-free full-bandwidth wavefronts.
            const float4* f4 = (const float4*)(Fs + (i * NC + c) * FP + wt * 4);
            float4 a0 = f4[0];
            float4 a1 = f4[1];
            unsigned long long fs[8];
            fs[0] = splat2(a0.x); fs[1] = splat2(a0.y);
            fs[2] = splat2(a0.z); fs[3] = splat2(a0.w);
            fs[4] = splat2(a1.x); fs[5] = splat2(a1.y);
            fs[6] = splat2(a1.z); fs[7] = splat2(a1.w);

            #pragma unroll
            for (int k = 0; k < KSZ; k++) {
                // one LDS.128 weight quad {o0..o0+3}; single address per warp (broadcast)
                ulonglong2 wq = *(const ulonglong2*)
                    &Wc[((i * KSZ + k) * NC + c) * O_DIM + o0];
                #pragma unroll
                for (int u = 0; u < 4; u++) {
                    ffma2(acc[0][u], wq.x, fs[u + k]);
                    ffma2(acc[1][u], wq.y, fs[u + k]);
                }
            }
        }
    }

    // ---- Phase 4: store. 4 o-rows x 4 consecutive w per thread. ----
    const int wbase = w0 + wt * 4;
    const bool full = (wbase + 4 <= W_OUT);
    #pragma unroll
    for (int p = 0; p < 2; p++) {
        float lv[4], hv[4];
        #pragma unroll
        for (int u = 0; u < 4; u++) {
            lv[u] = lo32(acc[p][u]);
            hv[u] = hi32(acc[p][u]);
        }
        int olo = o0 + 2 * p;
        float* rlo = out + ((size_t)(b * O_DIM + olo)) * W_OUT + wbase;
        float* rhi = rlo + W_OUT;
        if (full) {
            *(float4*)rlo = make_float4(lv[0], lv[1], lv[2], lv[3]);
            *(float4*)rhi = make_float4(hv[0], hv[1], hv[2], hv[3]);
        } else {
            #pragma unroll
            for (int u = 0; u < 4; u++) {
                if (wbase + u < W_OUT) {
                    rlo[u] = lv[u];
                    rhi[u] = hv[u];
                }
            }
        }
    }
}

extern "C" void kernel_launch(void* const* d_in, const int* in_sizes, int n_in,
                              void* d_out, int out_size)
{
    const float* x             = (const float*)d_in[0];
    const float* base_weight   = (const float*)d_in[1];
    const float* spline_weight = (const float*)d_in[2];
    const float* spline_scaler = (const float*)d_in[3];
    float* out = (float*)d_out;

    size_t smem_bytes = SMEM_FLOATS * sizeof(float);   // 84096
    cudaFuncSetAttribute(kan_conv1d_kernel,
                         cudaFuncAttributeMaxDynamicSharedMemorySize,
                         (int)smem_bytes);

    dim3 grid(NTILES, B_DIM);   // 64 x 32
    kan_conv1d_kernel<<<grid, NTHREADS, smem_bytes>>>(
        x, base_weight, spline_weight, spline_scaler, out);
}